// round 3
// baseline (speedup 1.0000x reference)
#include <cuda_runtime.h>

#define RAD 3
#define WIN 49            // (2*RAD+1)^2
#define NN  128
#define KCH 131
#define CCH 21
#define BB  2

// ---------------- scratch: A[b][w][i][j] ----------------
__device__ float g_A[BB * WIN * NN * NN];   // 6.4 MB

// ================= kernel 1: per-pixel window weights =================
// A[p, w] = m[p] * sum_k cp[k] * exp(|xm[k,p] - xm[k,p+o_w]|) / S_k(p)
// using exp(|a-b|) = max(E_a*R_b, E_b*R_a), E=exp(v), R=exp(-v),
// with (E,R)=(0,0) for out-of-grid halo cells (== reference `valid` mask).

#define T1H 8
#define T1W 16
#define NT1 (T1H * T1W)           // 128 threads
#define H1H (T1H + 2 * RAD)       // 14
#define H1W (T1W + 2 * RAD)       // 22
#define NFILL ((H1H * H1W + NT1 - 1) / NT1)   // 3

__global__ __launch_bounds__(NT1)
void rwn_weights_kernel(const float* __restrict__ feats,   // [B,K,N,N]
                        const int*   __restrict__ mask,    // [B,N,N]
                        const float* __restrict__ cp)      // [K]
{
    __shared__ float2 sER[H1H * H1W];

    const int b  = blockIdx.z;
    const int bi = blockIdx.y * T1H;
    const int bj = blockIdx.x * T1W;
    const int t  = threadIdx.x;
    const int ti = t / T1W, tj = t % T1W;
    const int gi = bi + ti, gj = bj + tj;

    const int*   mb = mask  + b * NN * NN;
    const float* fb = feats + (size_t)b * KCH * NN * NN;

    // precompute this thread's smem-fill slots (plane offset, mask value, validity)
    int   foff[NFILL];
    float fmsk[NFILL];
    bool  fok [NFILL];
    #pragma unroll
    for (int s = 0; s < NFILL; s++) {
        int idx = t + s * NT1;
        foff[s] = 0; fmsk[s] = 0.f; fok[s] = false;
        if (idx < H1H * H1W) {
            int hi = idx / H1W, hj = idx % H1W;
            int ggi = bi + hi - RAD, ggj = bj + hj - RAD;
            if (ggi >= 0 && ggi < NN && ggj >= 0 && ggj < NN) {
                fok[s]  = true;
                foff[s] = ggi * NN + ggj;
                fmsk[s] = (float)mb[foff[s]];
            }
        }
    }
    const float myM = (float)mb[gi * NN + gj];

    float Aw[WIN];
    #pragma unroll
    for (int w = 0; w < WIN; w++) Aw[w] = 0.f;

    #pragma unroll 1
    for (int k = 0; k < KCH; k++) {
        const float* fk = fb + (size_t)k * NN * NN;
        __syncthreads();                       // previous iter done reading sER
        #pragma unroll
        for (int s = 0; s < NFILL; s++) {
            int idx = t + s * NT1;
            if (idx < H1H * H1W) {
                float ex = 0.f, rx = 0.f;
                if (fok[s]) {
                    float v = __ldg(fk + foff[s]) * fmsk[s];
                    ex = __expf(v);
                    rx = __expf(-v);
                }
                sER[idx] = make_float2(ex, rx);
            }
        }
        __syncthreads();

        if (myM != 0.f) {
            const float2 c = sER[(ti + RAD) * H1W + (tj + RAD)];
            float ew[WIN];
            float ssum = 0.f;
            #pragma unroll
            for (int oi = 0; oi < 2 * RAD + 1; oi++) {
                #pragma unroll
                for (int oj = 0; oj < 2 * RAD + 1; oj++) {
                    float2 nb = sER[(ti + oi) * H1W + (tj + oj)];
                    float  e  = fmaxf(c.x * nb.y, c.y * nb.x);
                    ssum += e;
                    ew[oi * (2 * RAD + 1) + oj] = e;
                }
            }
            const float scale = __fdividef(__ldg(cp + k), ssum);
            #pragma unroll
            for (int w = 0; w < WIN; w++) Aw[w] += scale * ew[w];
        }
    }

    float* Ab = g_A + (size_t)b * WIN * NN * NN;
    #pragma unroll
    for (int w = 0; w < WIN; w++)
        Ab[(size_t)w * NN * NN + gi * NN + gj] = Aw[w];   // 0 for unmasked pixels
}

// ================= kernel 2: gather y[q,c] = sum_w A[q-o_w, w] * x2[c, q-o_w] =================

#define T2H 16
#define T2W 16
#define NT2 (T2H * T2W)
#define H2  (T2H + 2 * RAD)       // 22

__global__ __launch_bounds__(NT2)
void rwn_gather_kernel(const float* __restrict__ x2,   // [B,C,N*N]
                       float* __restrict__ out)        // [B,N*N,C]
{
    __shared__ float sX[CCH][H2 * H2];   // 21*484*4 = 40656 B

    const int b  = blockIdx.z;
    const int bi = blockIdx.y * T2H;
    const int bj = blockIdx.x * T2W;
    const int t  = threadIdx.x;
    const int ti = t / T2W, tj = t % T2W;
    const int qi = bi + ti, qj = bj + tj;

    const float* xb = x2 + (size_t)b * CCH * NN * NN;
    for (int idx = t; idx < CCH * H2 * H2; idx += NT2) {
        int c  = idx / (H2 * H2);
        int r  = idx % (H2 * H2);
        int hi = r / H2, hj = r % H2;
        int gi = bi + hi - RAD, gj = bj + hj - RAD;
        float v = 0.f;
        if (gi >= 0 && gi < NN && gj >= 0 && gj < NN)
            v = __ldg(xb + c * NN * NN + gi * NN + gj);
        sX[c][r] = v;
    }
    __syncthreads();

    float acc[CCH];
    #pragma unroll
    for (int c = 0; c < CCH; c++) acc[c] = 0.f;

    const float* Ab = g_A + (size_t)b * WIN * NN * NN;

    #pragma unroll
    for (int oi = -RAD; oi <= RAD; oi++) {
        #pragma unroll
        for (int oj = -RAD; oj <= RAD; oj++) {
            const int w  = (oi + RAD) * (2 * RAD + 1) + (oj + RAD);
            const int pi = qi - oi, pj = qj - oj;
            if (pi < 0 || pi >= NN || pj < 0 || pj >= NN) continue;
            const float a = Ab[(size_t)w * NN * NN + pi * NN + pj];
            const int sidx = (ti + RAD - oi) * H2 + (tj + RAD - oj);
            #pragma unroll
            for (int c = 0; c < CCH; c++)
                acc[c] += a * sX[c][sidx];
        }
    }

    float* ob = out + ((size_t)b * NN * NN + qi * NN + qj) * CCH;
    #pragma unroll
    for (int c = 0; c < CCH; c++) ob[c] = acc[c];
}

// ================= launch =================
extern "C" void kernel_launch(void* const* d_in, const int* in_sizes, int n_in,
                              void* d_out, int out_size)
{
    const float* feats = (const float*)d_in[0];   // intergrated [B,K,N,N]
    const float* x2    = (const float*)d_in[1];   // [B,C,N*N]
    const int*   mask  = (const int*)  d_in[2];   // [B,N,N]
    const float* cp    = (const float*)d_in[3];   // [K]
    float*       out   = (float*)d_out;           // [B,N*N,C]

    dim3 g1(NN / T1W, NN / T1H, BB);   // (8,16,2) = 256 blocks
    rwn_weights_kernel<<<g1, NT1>>>(feats, mask, cp);

    dim3 g2(NN / T2W, NN / T2H, BB);   // (8,8,2) = 128 blocks
    rwn_gather_kernel<<<g2, NT2>>>(x2, out);
}

// round 4
// speedup vs baseline: 1.5265x; 1.5265x over previous
#include <cuda_runtime.h>

#define RAD 3
#define WIN 49            // (2*RAD+1)^2
#define NN  128
#define KCH 131
#define CCH 21
#define BB  2
#define NS  4             // k-slices

// ---------------- scratch ----------------
__device__ float g_Apart[NS * BB * WIN * NN * NN];  // 25.6 MB partials
__device__ float g_A    [BB * WIN * NN * NN];       // 6.4 MB reduced

// ================= kernel 1: per-pixel window weights (k-sliced) =================
// A[p,w] += m[p] * sum_{k in slice} cp[k] * e[k,p,w] / S_k(p)
// e = exp(|v_c - v_n|) = max(E_n*R_c, R_n*E_c),  E=exp(v), R=exp(-v)
// halo-out-of-grid cells carry (E,R)=(0,0)  (== reference `valid` mask).

#define T1H 8
#define T1W 16
#define NT1 (T1H * T1W)           // 128 threads
#define H1H (T1H + 2 * RAD)       // 14
#define H1W (T1W + 2 * RAD)       // 22
#define HSZ (H1H * H1W)           // 308
#define NFILL ((HSZ + NT1 - 1) / NT1)   // 3

__global__ __launch_bounds__(NT1)
void rwn_weights_kernel(const float* __restrict__ feats,   // [B,K,N,N]
                        const int*   __restrict__ mask,    // [B,N,N]
                        const float* __restrict__ cp)      // [K]
{
    __shared__ float2 sER[2][HSZ];

    const int z  = blockIdx.z;
    const int b  = z % BB;
    const int sl = z / BB;
    const int bi = blockIdx.y * T1H;
    const int bj = blockIdx.x * T1W;
    const int t  = threadIdx.x;
    const int ti = t / T1W, tj = t % T1W;
    const int gi = bi + ti, gj = bj + tj;

    const int kbeg = (sl * KCH) / NS;
    const int kend = ((sl + 1) * KCH) / NS;

    const int*   mb = mask  + b * NN * NN;
    const float* fb = feats + (size_t)b * KCH * NN * NN;

    // precompute this thread's smem-fill slots
    int   foff[NFILL];
    float fmsk[NFILL];
    bool  fok [NFILL];
    #pragma unroll
    for (int s = 0; s < NFILL; s++) {
        int idx = t + s * NT1;
        foff[s] = 0; fmsk[s] = 0.f; fok[s] = false;
        if (idx < HSZ) {
            int hi = idx / H1W, hj = idx % H1W;
            int ggi = bi + hi - RAD, ggj = bj + hj - RAD;
            if (ggi >= 0 && ggi < NN && ggj >= 0 && ggj < NN) {
                fok[s]  = true;
                foff[s] = ggi * NN + ggj;
                fmsk[s] = (float)mb[foff[s]];
            }
        }
    }
    const float myM = (float)mb[gi * NN + gj];

    float Aw[WIN];
    #pragma unroll
    for (int w = 0; w < WIN; w++) Aw[w] = 0.f;

    // prologue fill: buffer 0 <- k = kbeg
    {
        const float* fk = fb + (size_t)kbeg * NN * NN;
        #pragma unroll
        for (int s = 0; s < NFILL; s++) {
            int idx = t + s * NT1;
            if (idx < HSZ) {
                float ex = 0.f, rx = 0.f;
                if (fok[s]) {
                    float v = __ldg(fk + foff[s]) * fmsk[s];
                    ex = __expf(v);
                    rx = __expf(-v);
                }
                sER[0][idx] = make_float2(ex, rx);
            }
        }
    }
    __syncthreads();

    #pragma unroll 1
    for (int k = kbeg; k < kend; k++) {
        const int cur = (k - kbeg) & 1;

        // fill next buffer (LDGs issued before the window compute)
        if (k + 1 < kend) {
            const float* fk = fb + (size_t)(k + 1) * NN * NN;
            #pragma unroll
            for (int s = 0; s < NFILL; s++) {
                int idx = t + s * NT1;
                if (idx < HSZ) {
                    float ex = 0.f, rx = 0.f;
                    if (fok[s]) {
                        float v = __ldg(fk + foff[s]) * fmsk[s];
                        ex = __expf(v);
                        rx = __expf(-v);
                    }
                    sER[cur ^ 1][idx] = make_float2(ex, rx);
                }
            }
        }

        if (myM != 0.f) {
            const float2 c = sER[cur][(ti + RAD) * H1W + (tj + RAD)];
            // packed (R_c, E_c): lo multiplies E_n, hi multiplies R_n
            const unsigned long long cs =
                (unsigned long long)__float_as_uint(c.y) |
                ((unsigned long long)__float_as_uint(c.x) << 32);
            const unsigned long long* sb =
                (const unsigned long long*)&sER[cur][0];

            float ew[WIN];
            float ss[4] = {0.f, 0.f, 0.f, 0.f};
            #pragma unroll
            for (int oi = 0; oi < 2 * RAD + 1; oi++) {
                #pragma unroll
                for (int oj = 0; oj < 2 * RAD + 1; oj++) {
                    const int w = oi * (2 * RAD + 1) + oj;
                    unsigned long long nb = sb[(ti + oi) * H1W + (tj + oj)];
                    unsigned long long p;
                    asm("mul.rn.f32x2 %0, %1, %2;" : "=l"(p) : "l"(nb), "l"(cs));
                    float e = fmaxf(__uint_as_float((unsigned)p),
                                    __uint_as_float((unsigned)(p >> 32)));
                    ew[w] = e;
                    ss[w & 3] += e;
                }
            }
            const float ssum  = (ss[0] + ss[1]) + (ss[2] + ss[3]);
            const float scale = __fdividef(__ldg(cp + k), ssum);
            #pragma unroll
            for (int w = 0; w < WIN; w++) Aw[w] += scale * ew[w];
        }
        __syncthreads();
    }

    float* Ab = g_Apart + ((size_t)sl * BB + b) * WIN * NN * NN;
    #pragma unroll
    for (int w = 0; w < WIN; w++)
        Ab[(size_t)w * NN * NN + gi * NN + gj] = Aw[w];   // 0 for unmasked pixels
}

// ================= reduce: g_A = sum over NS partials =================

#define RED_TOT4 (BB * WIN * NN * NN / 4)   // 401408 float4
#define RED_THR  256

__global__ __launch_bounds__(RED_THR)
void rwn_reduce_kernel()
{
    const int i = blockIdx.x * RED_THR + threadIdx.x;
    const float4* p = (const float4*)g_Apart;
    float4 a = p[i];
    float4 b = p[i + RED_TOT4];
    float4 c = p[i + 2 * RED_TOT4];
    float4 d = p[i + 3 * RED_TOT4];
    float4 r;
    r.x = (a.x + b.x) + (c.x + d.x);
    r.y = (a.y + b.y) + (c.y + d.y);
    r.z = (a.z + b.z) + (c.z + d.z);
    r.w = (a.w + b.w) + (c.w + d.w);
    ((float4*)g_A)[i] = r;
}

// ================= kernel 2: gather (channel-grouped) =================
// y[q,c] = sum_w A[q-o_w, w] * x2[c, q-o_w]

#define T2H 16
#define T2W 16
#define NT2 (T2H * T2W)
#define H2  (T2H + 2 * RAD)       // 22
#define CG  7                     // channels per block
#define NG  (CCH / CG)            // 3 groups

__global__ __launch_bounds__(NT2)
void rwn_gather_kernel(const float* __restrict__ x2,   // [B,C,N*N]
                       float* __restrict__ out)        // [B,N*N,C]
{
    __shared__ float sX[CG][H2 * H2];   // 7*484*4 = 13552 B

    const int z  = blockIdx.z;
    const int b  = z % BB;
    const int cg = z / BB;
    const int bi = blockIdx.y * T2H;
    const int bj = blockIdx.x * T2W;
    const int t  = threadIdx.x;
    const int ti = t / T2W, tj = t % T2W;
    const int qi = bi + ti, qj = bj + tj;

    const float* xb = x2 + ((size_t)b * CCH + cg * CG) * NN * NN;
    for (int idx = t; idx < CG * H2 * H2; idx += NT2) {
        int c  = idx / (H2 * H2);
        int r  = idx % (H2 * H2);
        int hi = r / H2, hj = r % H2;
        int gi = bi + hi - RAD, gj = bj + hj - RAD;
        float v = 0.f;
        if (gi >= 0 && gi < NN && gj >= 0 && gj < NN)
            v = __ldg(xb + c * NN * NN + gi * NN + gj);
        sX[c][r] = v;
    }
    __syncthreads();

    float acc[CG];
    #pragma unroll
    for (int c = 0; c < CG; c++) acc[c] = 0.f;

    const float* Ab = g_A + (size_t)b * WIN * NN * NN;

    #pragma unroll
    for (int oi = -RAD; oi <= RAD; oi++) {
        #pragma unroll
        for (int oj = -RAD; oj <= RAD; oj++) {
            const int w  = (oi + RAD) * (2 * RAD + 1) + (oj + RAD);
            const int pi = qi - oi, pj = qj - oj;
            if (pi < 0 || pi >= NN || pj < 0 || pj >= NN) continue;
            const float a = __ldg(Ab + (size_t)w * NN * NN + pi * NN + pj);
            const int sidx = (ti + RAD - oi) * H2 + (tj + RAD - oj);
            #pragma unroll
            for (int c = 0; c < CG; c++)
                acc[c] += a * sX[c][sidx];
        }
    }

    float* ob = out + ((size_t)b * NN * NN + qi * NN + qj) * CCH + cg * CG;
    #pragma unroll
    for (int c = 0; c < CG; c++) ob[c] = acc[c];
}

// ================= launch =================
extern "C" void kernel_launch(void* const* d_in, const int* in_sizes, int n_in,
                              void* d_out, int out_size)
{
    const float* feats = (const float*)d_in[0];   // intergrated [B,K,N,N]
    const float* x2    = (const float*)d_in[1];   // [B,C,N*N]
    const int*   mask  = (const int*)  d_in[2];   // [B,N,N]
    const float* cp    = (const float*)d_in[3];   // [K]
    float*       out   = (float*)d_out;           // [B,N*N,C]

    dim3 g1(NN / T1W, NN / T1H, BB * NS);     // (8,16,8) = 1024 blocks
    rwn_weights_kernel<<<g1, NT1>>>(feats, mask, cp);

    rwn_reduce_kernel<<<RED_TOT4 / RED_THR, RED_THR>>>();   // 1568 blocks

    dim3 g2(NN / T2W, NN / T2H, BB * NG);     // (8,8,6) = 384 blocks
    rwn_gather_kernel<<<g2, NT2>>>(x2, out);
}